// round 1
// baseline (speedup 1.0000x reference)
#include <cuda_runtime.h>
#include <math.h>

#define NTOK 1280
#define DMOD 512
#define NH   16
#define DH   32
#define DFF  2048
#define NITER 20

// ---------------- scratch (device globals; no allocation allowed) ----------------
__device__ float g_logK [NH*NTOK*NTOK];   // (h, n, m)
__device__ float g_logKT[NH*NTOK*NTOK];   // (h, m, n)
__device__ float g_hn [NTOK*DMOD];
__device__ float g_q  [NTOK*DMOD];
__device__ float g_k  [NTOK*DMOD];
__device__ float g_v  [NTOK*DMOD];
__device__ float g_gate[NTOK*DMOD];
__device__ float g_lu [NH*NTOK];
__device__ float g_lv [NH*NTOK];
__device__ float g_xc [NH*NTOK*3];
__device__ float g_rows[NH*NTOK];
__device__ float g_o  [NTOK*DMOD];
__device__ float g_h2 [NTOK*DMOD];
__device__ float g_hf [NTOK*DMOD];
__device__ float g_t1 [NTOK*DFF];
__device__ float g_t2 [NTOK*DFF];

__constant__ float c_eps[NH] = {0.5f,0.5f,0.5f,0.5f, 1.f,1.f,1.f,1.f,
                                2.f,2.f,2.f,2.f, 4.f,4.f,4.f,4.f};

// ---------------- small utility kernels ----------------
__global__ void zero_kernel(float* p, int n) {
    int i = blockIdx.x * blockDim.x + threadIdx.x;
    if (i < n) p[i] = 0.f;
}

__global__ void copy_uv_kernel(const float* __restrict__ lu, const float* __restrict__ lv,
                               float* __restrict__ o1, float* __restrict__ o2) {
    int i = blockIdx.x * blockDim.x + threadIdx.x;
    if (i < NH*NTOK) { o1[i] = lu[i]; o2[i] = lv[i]; }
}

// LayerNorm over D=512, block per row, 256 threads (2 elems/thread)
__global__ void ln_kernel(const float* __restrict__ in, const float* __restrict__ g,
                          const float* __restrict__ b, float* __restrict__ out) {
    int row = blockIdx.x;
    int t = threadIdx.x;
    const float* x = in + (size_t)row * DMOD;
    float v0 = x[t], v1 = x[t + 256];
    __shared__ float red[256];
    red[t] = v0 + v1;
    __syncthreads();
    for (int o = 128; o > 0; o >>= 1) { if (t < o) red[t] += red[t + o]; __syncthreads(); }
    float mean = red[0] * (1.f / DMOD);
    __syncthreads();
    float d0 = v0 - mean, d1 = v1 - mean;
    red[t] = d0 * d0 + d1 * d1;
    __syncthreads();
    for (int o = 128; o > 0; o >>= 1) { if (t < o) red[t] += red[t + o]; __syncthreads(); }
    float r = rsqrtf(red[0] * (1.f / DMOD) + 1e-5f);
    out[(size_t)row * DMOD + t]       = d0 * r * g[t]       + b[t];
    out[(size_t)row * DMOD + t + 256] = d1 * r * g[t + 256] + b[t + 256];
}

// per-head QK layernorm (groups of 32), in-place. 8 warps/block, warp per group.
__global__ void qkln_kernel(float* __restrict__ q) {
    int gidx = blockIdx.x * 8 + (threadIdx.x >> 5);
    int lane = threadIdx.x & 31;
    if (gidx >= NTOK * NH) return;
    int n = gidx / NH, h = gidx % NH;
    float* p = q + (size_t)n * DMOD + h * DH;
    float v = p[lane];
    float s = v;
    for (int o = 16; o; o >>= 1) s += __shfl_xor_sync(0xffffffffu, s, o);
    float mean = s * (1.f / 32.f);
    float d = v - mean;
    float s2 = d * d;
    for (int o = 16; o; o >>= 1) s2 += __shfl_xor_sync(0xffffffffu, s2, o);
    p[lane] = d * rsqrtf(s2 * (1.f / 32.f) + 1e-5f);
}

// generic SGEMM:  C[M,Nn] = A[M,K] * B[Nn,K]^T (+ R)   (NT, both row-major K-contig)
// 64x64 tile, BK=16, 256 threads, 4x4 per thread. Dims must divide tiles (they do).
__global__ void sgemm_nt(const float* __restrict__ A, const float* __restrict__ B,
                         const float* __restrict__ R, float* __restrict__ C,
                         int Nn, int K) {
    __shared__ float As[16][64];
    __shared__ float Bs[16][64];
    int t = threadIdx.x;
    int m0 = blockIdx.y * 64, n0 = blockIdx.x * 64;
    int lr = t >> 2, lc = (t & 3) << 2;
    int tm = t >> 4, tn = t & 15;
    float acc[4][4] = {};
    const float* Ap = A + (size_t)(m0 + lr) * K + lc;
    const float* Bp = B + (size_t)(n0 + lr) * K + lc;
    for (int k0 = 0; k0 < K; k0 += 16) {
        float4 a4 = *(const float4*)(Ap + k0);
        float4 b4 = *(const float4*)(Bp + k0);
        As[lc + 0][lr] = a4.x; As[lc + 1][lr] = a4.y; As[lc + 2][lr] = a4.z; As[lc + 3][lr] = a4.w;
        Bs[lc + 0][lr] = b4.x; Bs[lc + 1][lr] = b4.y; Bs[lc + 2][lr] = b4.z; Bs[lc + 3][lr] = b4.w;
        __syncthreads();
#pragma unroll
        for (int k = 0; k < 16; k++) {
            float4 av = *(const float4*)&As[k][tm << 2];
            float4 bv = *(const float4*)&Bs[k][tn << 2];
            float a[4] = {av.x, av.y, av.z, av.w};
            float bb[4] = {bv.x, bv.y, bv.z, bv.w};
#pragma unroll
            for (int i = 0; i < 4; i++)
#pragma unroll
                for (int j = 0; j < 4; j++) acc[i][j] += a[i] * bb[j];
        }
        __syncthreads();
    }
#pragma unroll
    for (int i = 0; i < 4; i++) {
        int row = m0 + (tm << 2) + i;
        float* Cp = C + (size_t)row * Nn + n0 + (tn << 2);
        if (R) {
            const float* Rp = R + (size_t)row * Nn + n0 + (tn << 2);
            Cp[0] = acc[i][0] + Rp[0]; Cp[1] = acc[i][1] + Rp[1];
            Cp[2] = acc[i][2] + Rp[2]; Cp[3] = acc[i][3] + Rp[3];
        } else {
            float4 o4 = make_float4(acc[i][0], acc[i][1], acc[i][2], acc[i][3]);
            *(float4*)Cp = o4;
        }
    }
}

// build logK and logK^T:
// logK[h,n,m] = (Qn[h,n,:].Kn[h,m,:]/sqrt(32) + wrel[h,n,m] - wdist[h]*d2(n,m)/100)/eps[h]
__global__ void build_logk(const float* __restrict__ wrel, const float* __restrict__ xres,
                           const float* __restrict__ wdist) {
    int h = blockIdx.z;
    int n0 = blockIdx.y * 32, m0 = blockIdx.x * 32;
    __shared__ float Qs[32][33], Ks[32][33], S[32][33];
    __shared__ float xa[32][3], xb[32][3];
    int t = threadIdx.x;
    for (int i = t; i < 1024; i += 256) {
        int r = i >> 5, d = i & 31;
        Qs[r][d] = g_q[(size_t)(n0 + r) * DMOD + h * DH + d];
        Ks[r][d] = g_k[(size_t)(m0 + r) * DMOD + h * DH + d];
    }
    if (t < 96)  { int r = t / 3, c = t % 3; xa[r][c] = xres[(n0 + r) * 3 + c]; }
    if (t >= 96 && t < 192) { int u = t - 96; int r = u / 3, c = u % 3; xb[r][c] = xres[(m0 + r) * 3 + c]; }
    __syncthreads();
    float inve = 1.f / c_eps[h];
    float wd = wdist[h] * 0.01f;
    const float scale = 0.17677669529663687f;  // 1/sqrt(32)
    int tm = t & 31, tn = t >> 5;
#pragma unroll
    for (int rr = 0; rr < 4; rr++) {
        int nl = tn + rr * 8;
        float acc = 0.f;
#pragma unroll
        for (int d = 0; d < 32; d++) acc += Qs[nl][d] * Ks[tm][d];
        float dx = xa[nl][0] - xb[tm][0];
        float dy = xa[nl][1] - xb[tm][1];
        float dz = xa[nl][2] - xb[tm][2];
        float d2 = dx * dx + dy * dy + dz * dz;
        size_t idx = ((size_t)h * NTOK + n0 + nl) * NTOK + m0 + tm;
        float val = (acc * scale + wrel[idx] - wd * d2) * inve;
        g_logK[idx] = val;
        S[nl][tm] = val;
    }
    __syncthreads();
#pragma unroll
    for (int rr = 0; rr < 4; rr++) {
        int ml = tn + rr * 8;
        g_logKT[((size_t)h * NTOK + m0 + ml) * NTOK + n0 + tm] = S[tm][ml];
    }
}

// one Sinkhorn half-step: out[h,r] = fi*(log(max(marg,1e-8)) - LSE_j(mat[h,r,j] + bias[h,j]))
// warp per row, 8 rows per block; grid (NTOK/8, NH)
__global__ void sinkhorn_pass(const float* __restrict__ mat, const float* __restrict__ bias,
                              const float* __restrict__ marg, float* __restrict__ out) {
    int h = blockIdx.y;
    __shared__ float bs[NTOK];
    for (int i = threadIdx.x; i < NTOK; i += 256) bs[i] = bias[h * NTOK + i];
    __syncthreads();
    int warp = threadIdx.x >> 5, lane = threadIdx.x & 31;
    int row = blockIdx.x * 8 + warp;
    const float* p = mat + ((size_t)h * NTOK + row) * NTOK;
    float m = -1e30f, s = 0.f;
    for (int j = lane; j < NTOK; j += 32) {
        float x = p[j] + bs[j];
        float nm = fmaxf(m, x);
        s = s * __expf(m - nm) + __expf(x - nm);
        m = nm;
    }
    for (int o = 16; o; o >>= 1) {
        float mo = __shfl_xor_sync(0xffffffffu, m, o);
        float so = __shfl_xor_sync(0xffffffffu, s, o);
        float nm = fmaxf(m, mo);
        s = s * __expf(m - nm) + so * __expf(mo - nm);
        m = nm;
    }
    if (lane == 0) {
        float fi = 1.f / (1.f + c_eps[h]);
        out[h * NTOK + row] = fi * (logf(fmaxf(marg[h * NTOK + row], 1e-8f)) - (m + logf(s)));
    }
}

// fused P application: P=exp(lu+logK+lv); accumulate attn=P.V, xc_num=P.x, rows=sum P.
// Also applies sigmoid gate into g_o. warp per (h,row); grid (NTOK/8, NH)
__global__ void papply_kernel(const float* __restrict__ xres) {
    int h = blockIdx.y;
    int warp = threadIdx.x >> 5, lane = threadIdx.x & 31;
    int row = blockIdx.x * 8 + warp;
    __shared__ float lvs[NTOK];
    __shared__ float xs[3 * NTOK];
    __shared__ float vs[128 * 32];
    for (int i = threadIdx.x; i < NTOK; i += 256) lvs[i] = g_lv[h * NTOK + i];
    for (int i = threadIdx.x; i < 3 * NTOK; i += 256) xs[i] = xres[i];
    float lu_r = g_lu[h * NTOK + row];
    float acc = 0.f, ax = 0.f, psum = 0.f;
    for (int mc = 0; mc < NTOK; mc += 128) {
        __syncthreads();
        for (int i = threadIdx.x; i < 128 * 32; i += 256) {
            int r = i >> 5, d = i & 31;
            vs[i] = g_v[(size_t)(mc + r) * DMOD + h * DH + d];
        }
        __syncthreads();
        const float* lk = g_logK + ((size_t)h * NTOK + row) * NTOK + mc;
#pragma unroll
        for (int mj = 0; mj < 128; mj += 32) {
            float pl = __expf(lk[mj + lane] + lvs[mc + mj + lane] + lu_r);
            psum += pl;
#pragma unroll
            for (int j = 0; j < 32; j++) {
                float p = __shfl_sync(0xffffffffu, pl, j);
                acc += p * vs[(mj + j) * 32 + lane];
                if (lane < 3) ax += p * xs[(mc + mj + j) * 3 + lane];
            }
        }
    }
    float ps = psum;
    for (int o = 16; o; o >>= 1) ps += __shfl_xor_sync(0xffffffffu, ps, o);
    size_t off = (size_t)row * DMOD + h * DH + lane;
    float gt = g_gate[off];
    g_o[off] = acc / (1.f + __expf(-gt));
    if (lane < 3) g_xc[((size_t)h * NTOK + row) * 3 + lane] = ax;
    if (lane == 0) g_rows[h * NTOK + row] = ps;
}

__global__ void xout_kernel(const float* __restrict__ xres, const float* __restrict__ gamma,
                            float* __restrict__ out) {
    int n = blockIdx.x * 256 + threadIdx.x;
    if (n >= NTOK) return;
    float x0 = xres[n * 3 + 0], x1 = xres[n * 3 + 1], x2 = xres[n * 3 + 2];
    float a0 = 0.f, a1 = 0.f, a2 = 0.f;
    for (int h = 0; h < NH; h++) {
        float r = 1.f / (g_rows[h * NTOK + n] + 1e-8f);
        float gm = gamma[h];
        a0 += gm * (x0 - g_xc[((size_t)h * NTOK + n) * 3 + 0] * r);
        a1 += gm * (x1 - g_xc[((size_t)h * NTOK + n) * 3 + 1] * r);
        a2 += gm * (x2 - g_xc[((size_t)h * NTOK + n) * 3 + 2] * r);
    }
    out[n * 3 + 0] = x0 + a0;
    out[n * 3 + 1] = x1 + a1;
    out[n * 3 + 2] = x2 + a2;
}

__global__ void silumul_kernel(float* __restrict__ t1, const float* __restrict__ t2) {
    int i = blockIdx.x * 256 + threadIdx.x;
    if (i < NTOK * DFF) {
        float a = t1[i];
        t1[i] = a / (1.f + __expf(-a)) * t2[i];
    }
}

// ---------------- launch ----------------
extern "C" void kernel_launch(void* const* d_in, const int* in_sizes, int n_in,
                              void* d_out, int out_size) {
    const float* h_in  = (const float*)d_in[0];
    const float* x_res = (const float*)d_in[1];
    const float* mu    = (const float*)d_in[2];
    const float* nu    = (const float*)d_in[3];
    const float* wrel  = (const float*)d_in[4];
    const float* wdist = (const float*)d_in[5];
    // d_in[6] = pos_bins (unused by reference)
    const float* ln_ag = (const float*)d_in[7];
    const float* ln_ab = (const float*)d_in[8];
    const float* Wq    = (const float*)d_in[9];
    const float* Wk    = (const float*)d_in[10];
    const float* Wv    = (const float*)d_in[11];
    const float* Wg    = (const float*)d_in[12];
    const float* Wo    = (const float*)d_in[13];
    const float* gamma = (const float*)d_in[14];
    const float* ln_fg = (const float*)d_in[15];
    const float* ln_fb = (const float*)d_in[16];
    const float* W1    = (const float*)d_in[17];
    const float* W2    = (const float*)d_in[18];
    const float* W3    = (const float*)d_in[19];
    float* out = (float*)d_out;

    float *p_logK, *p_logKT, *p_hn, *p_q, *p_k, *p_v, *p_gate, *p_lu, *p_lv,
          *p_o, *p_h2, *p_hf, *p_t1, *p_t2;
    cudaGetSymbolAddress((void**)&p_logK,  g_logK);
    cudaGetSymbolAddress((void**)&p_logKT, g_logKT);
    cudaGetSymbolAddress((void**)&p_hn,    g_hn);
    cudaGetSymbolAddress((void**)&p_q,     g_q);
    cudaGetSymbolAddress((void**)&p_k,     g_k);
    cudaGetSymbolAddress((void**)&p_v,     g_v);
    cudaGetSymbolAddress((void**)&p_gate,  g_gate);
    cudaGetSymbolAddress((void**)&p_lu,    g_lu);
    cudaGetSymbolAddress((void**)&p_lv,    g_lv);
    cudaGetSymbolAddress((void**)&p_o,     g_o);
    cudaGetSymbolAddress((void**)&p_h2,    g_h2);
    cudaGetSymbolAddress((void**)&p_hf,    g_hf);
    cudaGetSymbolAddress((void**)&p_t1,    g_t1);
    cudaGetSymbolAddress((void**)&p_t2,    g_t2);

    const int OUT_H  = 0;
    const int OUT_X  = NTOK * DMOD;                 // 655360
    const int OUT_LU = OUT_X + NTOK * 3;            // 659200
    const int OUT_LV = OUT_LU + NH * NTOK;          // 679680

    // init lv = 0
    zero_kernel<<<(NH * NTOK + 1023) / 1024, 1024>>>(p_lv, NH * NTOK);

    // h_n = LN(h)
    ln_kernel<<<NTOK, 256>>>(h_in, ln_ag, ln_ab, p_hn);

    // projections
    dim3 g512(DMOD / 64, NTOK / 64);
    sgemm_nt<<<g512, 256>>>(p_hn, Wq, nullptr, p_q, DMOD, DMOD);
    sgemm_nt<<<g512, 256>>>(p_hn, Wk, nullptr, p_k, DMOD, DMOD);
    sgemm_nt<<<g512, 256>>>(p_hn, Wv, nullptr, p_v, DMOD, DMOD);
    sgemm_nt<<<g512, 256>>>(p_hn, Wg, nullptr, p_gate, DMOD, DMOD);

    // QK layernorm (per-head, in place)
    qkln_kernel<<<(NTOK * NH) / 8, 256>>>(p_q);
    qkln_kernel<<<(NTOK * NH) / 8, 256>>>(p_k);

    // logK + logK^T
    build_logk<<<dim3(NTOK / 32, NTOK / 32, NH), 256>>>(wrel, x_res, wdist);

    // Sinkhorn
    dim3 gsink(NTOK / 8, NH);
    for (int it = 0; it < NITER; it++) {
        sinkhorn_pass<<<gsink, 256>>>(p_logK,  p_lv, mu, p_lu);
        sinkhorn_pass<<<gsink, 256>>>(p_logKT, p_lu, nu, p_lv);
    }

    // fused P*V / P*x / rowsums + gating
    papply_kernel<<<gsink, 256>>>(x_res);

    // h2 = h + o @ Wo^T
    sgemm_nt<<<g512, 256>>>(p_o, Wo, h_in, p_h2, DMOD, DMOD);

    // x_out
    xout_kernel<<<(NTOK + 255) / 256, 256>>>(x_res, gamma, out + OUT_X);

    // FFN
    ln_kernel<<<NTOK, 256>>>(p_h2, ln_fg, ln_fb, p_hf);
    dim3 gff(DFF / 64, NTOK / 64);
    sgemm_nt<<<gff, 256>>>(p_hf, W1, nullptr, p_t1, DFF, DMOD);
    sgemm_nt<<<gff, 256>>>(p_hf, W2, nullptr, p_t2, DFF, DMOD);
    silumul_kernel<<<(NTOK * DFF) / 256, 256>>>(p_t1, p_t2);
    sgemm_nt<<<g512, 256>>>(p_t1, W3, p_h2, out + OUT_H, DMOD, DFF);

    // lu / lv outputs
    copy_uv_kernel<<<(NH * NTOK + 1023) / 1024, 1024>>>(p_lu, p_lv, out + OUT_LU, out + OUT_LV);
}

// round 2
// speedup vs baseline: 1.2838x; 1.2838x over previous
#include <cuda_runtime.h>
#include <cuda_fp16.h>
#include <math.h>

#define NTOK 1280
#define DMOD 512
#define NH   16
#define DH   32
#define DFF  2048
#define NITER 20

// ---------------- scratch (device globals; no allocation allowed) ----------------
__device__ __half g_logKh [NH*NTOK*NTOK];   // (h, n, m) fp16
__device__ __half g_logKTh[NH*NTOK*NTOK];   // (h, m, n) fp16
__device__ float g_hn  [NTOK*DMOD];
__device__ float g_qkvg[NTOK*4*DMOD];       // cols: [q | k | v | gate]
__device__ float g_lu [NH*NTOK];
__device__ float g_lv [NH*NTOK];
__device__ float g_xc [NH*NTOK*3];
__device__ float g_rows[NH*NTOK];
__device__ float g_o  [NTOK*DMOD];
__device__ float g_h2 [NTOK*DMOD];
__device__ float g_hf [NTOK*DMOD];
__device__ float g_t12[NTOK*2*DFF];         // [t1 | t2]
__device__ float g_t1 [NTOK*DFF];
__device__ float g_part[4*NTOK*DMOD];       // split-K partials

__constant__ float c_eps[NH] = {0.5f,0.5f,0.5f,0.5f, 1.f,1.f,1.f,1.f,
                                2.f,2.f,2.f,2.f, 4.f,4.f,4.f,4.f};

struct Ptr4 { const float* p[4]; };

// ---------------- small utility kernels ----------------
__global__ void zero_kernel(float* p, int n) {
    int i = blockIdx.x * blockDim.x + threadIdx.x;
    if (i < n) p[i] = 0.f;
}

__global__ void copy_uv_kernel(const float* __restrict__ lu, const float* __restrict__ lv,
                               float* __restrict__ o1, float* __restrict__ o2) {
    int i = blockIdx.x * blockDim.x + threadIdx.x;
    if (i < NH*NTOK) { o1[i] = lu[i]; o2[i] = lv[i]; }
}

// LayerNorm over D=512, block per row, 256 threads (2 elems/thread)
__global__ void ln_kernel(const float* __restrict__ in, const float* __restrict__ g,
                          const float* __restrict__ b, float* __restrict__ out) {
    int row = blockIdx.x;
    int t = threadIdx.x;
    const float* x = in + (size_t)row * DMOD;
    float v0 = x[t], v1 = x[t + 256];
    __shared__ float red[256];
    red[t] = v0 + v1;
    __syncthreads();
    for (int o = 128; o > 0; o >>= 1) { if (t < o) red[t] += red[t + o]; __syncthreads(); }
    float mean = red[0] * (1.f / DMOD);
    __syncthreads();
    float d0 = v0 - mean, d1 = v1 - mean;
    red[t] = d0 * d0 + d1 * d1;
    __syncthreads();
    for (int o = 128; o > 0; o >>= 1) { if (t < o) red[t] += red[t + o]; __syncthreads(); }
    float r = rsqrtf(red[0] * (1.f / DMOD) + 1e-5f);
    out[(size_t)row * DMOD + t]       = d0 * r * g[t]       + b[t];
    out[(size_t)row * DMOD + t + 256] = d1 * r * g[t + 256] + b[t + 256];
}

// per-head QK layernorm (groups of 32) in-place, row stride = 4*DMOD
__global__ void qkln_kernel(float* __restrict__ base) {
    int gidx = blockIdx.x * 8 + (threadIdx.x >> 5);
    int lane = threadIdx.x & 31;
    if (gidx >= NTOK * NH) return;
    int n = gidx / NH, h = gidx % NH;
    float* p = base + (size_t)n * (4*DMOD) + h * DH;
    float v = p[lane];
    float s = v;
    for (int o = 16; o; o >>= 1) s += __shfl_xor_sync(0xffffffffu, s, o);
    float mean = s * (1.f / 32.f);
    float d = v - mean;
    float s2 = d * d;
    for (int o = 16; o; o >>= 1) s2 += __shfl_xor_sync(0xffffffffu, s2, o);
    p[lane] = d * rsqrtf(s2 * (1.f / 32.f) + 1e-5f);
}

// batched SGEMM: C[M,Nn] = A[M,K] * Bsel^T, B selected per 64-col tile from 4 ptrs.
// 64x64 tile, BK=16, 256 threads, 4x4/thread.
__global__ void sgemm_nt4(const float* __restrict__ A, Ptr4 B4, float* __restrict__ C,
                          int Nn, int K, int colsPer) {
    __shared__ float As[16][64];
    __shared__ float Bs[16][64];
    int t = threadIdx.x;
    int m0 = blockIdx.y * 64, n0 = blockIdx.x * 64;
    const float* B = B4.p[n0 / colsPer] + (size_t)(n0 % colsPer) * K;
    int lr = t >> 2, lc = (t & 3) << 2;
    int tm = t >> 4, tn = t & 15;
    float acc[4][4] = {};
    const float* Ap = A + (size_t)(m0 + lr) * K + lc;
    const float* Bp = B + (size_t)lr * K + lc;
    for (int k0 = 0; k0 < K; k0 += 16) {
        float4 a4 = *(const float4*)(Ap + k0);
        float4 b4 = *(const float4*)(Bp + k0);
        As[lc + 0][lr] = a4.x; As[lc + 1][lr] = a4.y; As[lc + 2][lr] = a4.z; As[lc + 3][lr] = a4.w;
        Bs[lc + 0][lr] = b4.x; Bs[lc + 1][lr] = b4.y; Bs[lc + 2][lr] = b4.z; Bs[lc + 3][lr] = b4.w;
        __syncthreads();
#pragma unroll
        for (int k = 0; k < 16; k++) {
            float4 av = *(const float4*)&As[k][tm << 2];
            float4 bv = *(const float4*)&Bs[k][tn << 2];
            float a[4] = {av.x, av.y, av.z, av.w};
            float bb[4] = {bv.x, bv.y, bv.z, bv.w};
#pragma unroll
            for (int i = 0; i < 4; i++)
#pragma unroll
                for (int j = 0; j < 4; j++) acc[i][j] += a[i] * bb[j];
        }
        __syncthreads();
    }
#pragma unroll
    for (int i = 0; i < 4; i++) {
        int row = m0 + (tm << 2) + i;
        float* Cp = C + (size_t)row * Nn + n0 + (tn << 2);
        *(float4*)Cp = make_float4(acc[i][0], acc[i][1], acc[i][2], acc[i][3]);
    }
}

// split-K SGEMM: partial C for K-chunk blockIdx.z into g_part slice (no residual).
__global__ void sgemm_nt_splitk(const float* __restrict__ A, const float* __restrict__ B,
                                float* __restrict__ Cpart, int Nn, int K, int KC) {
    __shared__ float As[16][64];
    __shared__ float Bs[16][64];
    int t = threadIdx.x;
    int m0 = blockIdx.y * 64, n0 = blockIdx.x * 64;
    int kbeg = blockIdx.z * KC, kend = kbeg + KC;
    int lr = t >> 2, lc = (t & 3) << 2;
    int tm = t >> 4, tn = t & 15;
    float acc[4][4] = {};
    const float* Ap = A + (size_t)(m0 + lr) * K + lc;
    const float* Bp = B + (size_t)(n0 + lr) * K + lc;
    for (int k0 = kbeg; k0 < kend; k0 += 16) {
        float4 a4 = *(const float4*)(Ap + k0);
        float4 b4 = *(const float4*)(Bp + k0);
        As[lc + 0][lr] = a4.x; As[lc + 1][lr] = a4.y; As[lc + 2][lr] = a4.z; As[lc + 3][lr] = a4.w;
        Bs[lc + 0][lr] = b4.x; Bs[lc + 1][lr] = b4.y; Bs[lc + 2][lr] = b4.z; Bs[lc + 3][lr] = b4.w;
        __syncthreads();
#pragma unroll
        for (int k = 0; k < 16; k++) {
            float4 av = *(const float4*)&As[k][tm << 2];
            float4 bv = *(const float4*)&Bs[k][tn << 2];
            float a[4] = {av.x, av.y, av.z, av.w};
            float bb[4] = {bv.x, bv.y, bv.z, bv.w};
#pragma unroll
            for (int i = 0; i < 4; i++)
#pragma unroll
                for (int j = 0; j < 4; j++) acc[i][j] += a[i] * bb[j];
        }
        __syncthreads();
    }
    float* Co = Cpart + (size_t)blockIdx.z * NTOK * Nn;
#pragma unroll
    for (int i = 0; i < 4; i++) {
        int row = m0 + (tm << 2) + i;
        *(float4*)(Co + (size_t)row * Nn + n0 + (tn << 2)) =
            make_float4(acc[i][0], acc[i][1], acc[i][2], acc[i][3]);
    }
}

// out[i] = R[i] + sum_z part[z*n + i]
__global__ void reduce_add(const float* __restrict__ R, const float* __restrict__ part,
                           int Z, float* __restrict__ out, int n) {
    int i = blockIdx.x * 256 + threadIdx.x;
    if (i >= n) return;
    float a = R[i];
    for (int z = 0; z < Z; z++) a += part[(size_t)z * n + i];
    out[i] = a;
}

// build logK (fp16) and logK^T (fp16)
__global__ void build_logk(const float* __restrict__ wrel, const float* __restrict__ xres,
                           const float* __restrict__ wdist) {
    int h = blockIdx.z;
    int n0 = blockIdx.y * 32, m0 = blockIdx.x * 32;
    __shared__ float Qs[32][33], Ks[32][33], S[32][33];
    __shared__ float xa[32][3], xb[32][3];
    int t = threadIdx.x;
    for (int i = t; i < 1024; i += 256) {
        int r = i >> 5, d = i & 31;
        Qs[r][d] = g_qkvg[(size_t)(n0 + r) * (4*DMOD) + h * DH + d];
        Ks[r][d] = g_qkvg[(size_t)(m0 + r) * (4*DMOD) + DMOD + h * DH + d];
    }
    if (t < 96)  { int r = t / 3, c = t % 3; xa[r][c] = xres[(n0 + r) * 3 + c]; }
    if (t >= 96 && t < 192) { int u = t - 96; int r = u / 3, c = u % 3; xb[r][c] = xres[(m0 + r) * 3 + c]; }
    __syncthreads();
    float inve = 1.f / c_eps[h];
    float wd = wdist[h] * 0.01f;
    const float scale = 0.17677669529663687f;  // 1/sqrt(32)
    int tm = t & 31, tn = t >> 5;
#pragma unroll
    for (int rr = 0; rr < 4; rr++) {
        int nl = tn + rr * 8;
        float acc = 0.f;
#pragma unroll
        for (int d = 0; d < 32; d++) acc += Qs[nl][d] * Ks[tm][d];
        float dx = xa[nl][0] - xb[tm][0];
        float dy = xa[nl][1] - xb[tm][1];
        float dz = xa[nl][2] - xb[tm][2];
        float d2 = dx * dx + dy * dy + dz * dz;
        size_t idx = ((size_t)h * NTOK + n0 + nl) * NTOK + m0 + tm;
        float val = (acc * scale + wrel[idx] - wd * d2) * inve;
        g_logKh[idx] = __float2half(val);
        S[nl][tm] = val;
    }
    __syncthreads();
#pragma unroll
    for (int rr = 0; rr < 4; rr++) {
        int ml = tn + rr * 8;
        g_logKTh[((size_t)h * NTOK + m0 + ml) * NTOK + n0 + tm] = __float2half(S[tm][ml]);
    }
}

// merge two (m,s) LSE states with a single expf
__device__ __forceinline__ void lse_merge(float& m, float& s, float mo, float so) {
    float d = m - mo;
    float e = __expf(-fabsf(d));
    s = (d >= 0.f) ? (s + so * e) : (so + s * e);
    m = fmaxf(m, mo);
}

// one Sinkhorn half-step over fp16 matrix: out = fi*(log(marg) - LSE_j(mat[r,j]+bias[j]))
__global__ void sinkhorn_pass(const __half* __restrict__ mat, const float* __restrict__ bias,
                              const float* __restrict__ marg, float* __restrict__ out) {
    int h = blockIdx.y;
    __shared__ float bs[NTOK];
    for (int i = threadIdx.x; i < NTOK; i += 256) bs[i] = bias[h * NTOK + i];
    __syncthreads();
    int warp = threadIdx.x >> 5, lane = threadIdx.x & 31;
    int row = blockIdx.x * 8 + warp;
    const uint4* pv = (const uint4*)(mat + ((size_t)h * NTOK + row) * NTOK);
    float m = -1e30f, s = 0.f;
#pragma unroll
    for (int c = 0; c < 5; c++) {
        uint4 u = pv[c * 32 + lane];
        int jb = (c * 32 + lane) * 8;
        const __half2* hh = (const __half2*)&u;
        float2 f0 = __half22float2(hh[0]);
        float2 f1 = __half22float2(hh[1]);
        float2 f2 = __half22float2(hh[2]);
        float2 f3 = __half22float2(hh[3]);
        float x0 = f0.x + bs[jb + 0], x1 = f0.y + bs[jb + 1];
        float x2 = f1.x + bs[jb + 2], x3 = f1.y + bs[jb + 3];
        float x4 = f2.x + bs[jb + 4], x5 = f2.y + bs[jb + 5];
        float x6 = f3.x + bs[jb + 6], x7 = f3.y + bs[jb + 7];
        // pairwise LSEs (1 expf each)
        float ma = fmaxf(x0, x1), sa = 1.f + __expf(-fabsf(x0 - x1));
        float mb = fmaxf(x2, x3), sb = 1.f + __expf(-fabsf(x2 - x3));
        float mc = fmaxf(x4, x5), sc = 1.f + __expf(-fabsf(x4 - x5));
        float md = fmaxf(x6, x7), sd = 1.f + __expf(-fabsf(x6 - x7));
        lse_merge(ma, sa, mb, sb);
        lse_merge(mc, sc, md, sd);
        lse_merge(ma, sa, mc, sc);
        lse_merge(m, s, ma, sa);
    }
    for (int o = 16; o; o >>= 1) {
        float mo = __shfl_xor_sync(0xffffffffu, m, o);
        float so = __shfl_xor_sync(0xffffffffu, s, o);
        lse_merge(m, s, mo, so);
    }
    if (lane == 0) {
        float fi = 1.f / (1.f + c_eps[h]);
        out[h * NTOK + row] = fi * (logf(fmaxf(marg[h * NTOK + row], 1e-8f)) - (m + logf(s)));
    }
}

// fused P application: P=exp(lu+logK+lv); attn=P.V (gated), xc_num=P.x, rows=sum P.
__global__ void papply_kernel(const float* __restrict__ xres) {
    int h = blockIdx.y;
    int warp = threadIdx.x >> 5, lane = threadIdx.x & 31;
    int row = blockIdx.x * 8 + warp;
    __shared__ float lvs[NTOK];
    __shared__ float xs[3 * NTOK];
    __shared__ float vs[128 * 32];
    for (int i = threadIdx.x; i < NTOK; i += 256) lvs[i] = g_lv[h * NTOK + i];
    for (int i = threadIdx.x; i < 3 * NTOK; i += 256) xs[i] = xres[i];
    float lu_r = g_lu[h * NTOK + row];
    float acc = 0.f, ax = 0.f, psum = 0.f;
    for (int mc = 0; mc < NTOK; mc += 128) {
        __syncthreads();
        for (int i = threadIdx.x; i < 128 * 32; i += 256) {
            int r = i >> 5, d = i & 31;
            vs[i] = g_qkvg[(size_t)(mc + r) * (4*DMOD) + 2*DMOD + h * DH + d];
        }
        __syncthreads();
        const __half* lk = g_logKh + ((size_t)h * NTOK + row) * NTOK + mc;
#pragma unroll
        for (int mj = 0; mj < 128; mj += 32) {
            float pl = __expf(__half2float(lk[mj + lane]) + lvs[mc + mj + lane] + lu_r);
            psum += pl;
#pragma unroll
            for (int j = 0; j < 32; j++) {
                float p = __shfl_sync(0xffffffffu, pl, j);
                acc += p * vs[(mj + j) * 32 + lane];
                if (lane < 3) ax += p * xs[(mc + mj + j) * 3 + lane];
            }
        }
    }
    float ps = psum;
    for (int o = 16; o; o >>= 1) ps += __shfl_xor_sync(0xffffffffu, ps, o);
    float gt = g_qkvg[(size_t)row * (4*DMOD) + 3*DMOD + h * DH + lane];
    g_o[(size_t)row * DMOD + h * DH + lane] = acc / (1.f + __expf(-gt));
    if (lane < 3) g_xc[((size_t)h * NTOK + row) * 3 + lane] = ax;
    if (lane == 0) g_rows[h * NTOK + row] = ps;
}

__global__ void xout_kernel(const float* __restrict__ xres, const float* __restrict__ gamma,
                            float* __restrict__ out) {
    int n = blockIdx.x * 256 + threadIdx.x;
    if (n >= NTOK) return;
    float x0 = xres[n * 3 + 0], x1 = xres[n * 3 + 1], x2 = xres[n * 3 + 2];
    float a0 = 0.f, a1 = 0.f, a2 = 0.f;
    for (int h = 0; h < NH; h++) {
        float r = 1.f / (g_rows[h * NTOK + n] + 1e-8f);
        float gm = gamma[h];
        a0 += gm * (x0 - g_xc[((size_t)h * NTOK + n) * 3 + 0] * r);
        a1 += gm * (x1 - g_xc[((size_t)h * NTOK + n) * 3 + 1] * r);
        a2 += gm * (x2 - g_xc[((size_t)h * NTOK + n) * 3 + 2] * r);
    }
    out[n * 3 + 0] = x0 + a0;
    out[n * 3 + 1] = x1 + a1;
    out[n * 3 + 2] = x2 + a2;
}

// t1[n*DFF+j] = silu(t12[n][j]) * t12[n][DFF+j]
__global__ void silumul_kernel() {
    int i = blockIdx.x * 256 + threadIdx.x;
    if (i < NTOK * DFF) {
        int n = i >> 11, j = i & (DFF - 1);
        float a = g_t12[(size_t)n * (2*DFF) + j];
        float b = g_t12[(size_t)n * (2*DFF) + DFF + j];
        g_t1[i] = a / (1.f + __expf(-a)) * b;
    }
}

// ---------------- launch ----------------
extern "C" void kernel_launch(void* const* d_in, const int* in_sizes, int n_in,
                              void* d_out, int out_size) {
    const float* h_in  = (const float*)d_in[0];
    const float* x_res = (const float*)d_in[1];
    const float* mu    = (const float*)d_in[2];
    const float* nu    = (const float*)d_in[3];
    const float* wrel  = (const float*)d_in[4];
    const float* wdist = (const float*)d_in[5];
    // d_in[6] = pos_bins (unused)
    const float* ln_ag = (const float*)d_in[7];
    const float* ln_ab = (const float*)d_in[8];
    const float* Wq    = (const float*)d_in[9];
    const float* Wk    = (const float*)d_in[10];
    const float* Wv    = (const float*)d_in[11];
    const float* Wg    = (const float*)d_in[12];
    const float* Wo    = (const float*)d_in[13];
    const float* gamma = (const float*)d_in[14];
    const float* ln_fg = (const float*)d_in[15];
    const float* ln_fb = (const float*)d_in[16];
    const float* W1    = (const float*)d_in[17];
    const float* W2    = (const float*)d_in[18];
    const float* W3    = (const float*)d_in[19];
    float* out = (float*)d_out;

    __half *p_logKh, *p_logKTh;
    float *p_hn, *p_qkvg, *p_lu, *p_lv, *p_o, *p_h2, *p_hf, *p_t1, *p_part;
    cudaGetSymbolAddress((void**)&p_logKh,  g_logKh);
    cudaGetSymbolAddress((void**)&p_logKTh, g_logKTh);
    cudaGetSymbolAddress((void**)&p_hn,     g_hn);
    cudaGetSymbolAddress((void**)&p_qkvg,   g_qkvg);
    cudaGetSymbolAddress((void**)&p_lu,     g_lu);
    cudaGetSymbolAddress((void**)&p_lv,     g_lv);
    cudaGetSymbolAddress((void**)&p_o,      g_o);
    cudaGetSymbolAddress((void**)&p_h2,     g_h2);
    cudaGetSymbolAddress((void**)&p_hf,     g_hf);
    cudaGetSymbolAddress((void**)&p_t1,     g_t1);
    cudaGetSymbolAddress((void**)&p_part,   g_part);
    float* p_t12; cudaGetSymbolAddress((void**)&p_t12, g_t12);

    const int OUT_X  = NTOK * DMOD;                 // 655360
    const int OUT_LU = OUT_X + NTOK * 3;            // 659200
    const int OUT_LV = OUT_LU + NH * NTOK;          // 679680

    zero_kernel<<<(NH * NTOK + 1023) / 1024, 1024>>>(p_lv, NH * NTOK);

    // h_n = LN(h)
    ln_kernel<<<NTOK, 256>>>(h_in, ln_ag, ln_ab, p_hn);

    // batched QKVG projection: [1280, 2048] = hn @ [Wq;Wk;Wv;Wg]^T
    Ptr4 bqkvg; bqkvg.p[0] = Wq; bqkvg.p[1] = Wk; bqkvg.p[2] = Wv; bqkvg.p[3] = Wg;
    sgemm_nt4<<<dim3(4*DMOD/64, NTOK/64), 256>>>(p_hn, bqkvg, p_qkvg, 4*DMOD, DMOD, DMOD);

    // QK layernorm (per-head, in place)
    qkln_kernel<<<(NTOK * NH) / 8, 256>>>(p_qkvg);           // Q section
    qkln_kernel<<<(NTOK * NH) / 8, 256>>>(p_qkvg + DMOD);    // K section

    // logK + logK^T in fp16
    build_logk<<<dim3(NTOK / 32, NTOK / 32, NH), 256>>>(wrel, x_res, wdist);

    // Sinkhorn (L2-resident fp16)
    dim3 gsink(NTOK / 8, NH);
    for (int it = 0; it < NITER; it++) {
        sinkhorn_pass<<<gsink, 256>>>(p_logKh,  p_lv, mu, p_lu);
        sinkhorn_pass<<<gsink, 256>>>(p_logKTh, p_lu, nu, p_lv);
    }

    // fused P*V / P*x / rowsums + gating
    papply_kernel<<<gsink, 256>>>(x_res);

    // h2 = h + o @ Wo^T  (split-K=2, deterministic reduce)
    sgemm_nt_splitk<<<dim3(DMOD/64, NTOK/64, 2), 256>>>(p_o, Wo, p_part, DMOD, DMOD, DMOD/2);
    reduce_add<<<(NTOK*DMOD)/256, 256>>>(h_in, p_part, 2, p_h2, NTOK*DMOD);

    // x_out
    xout_kernel<<<(NTOK + 255) / 256, 256>>>(x_res, gamma, out + OUT_X);

    // FFN
    ln_kernel<<<NTOK, 256>>>(p_h2, ln_fg, ln_fb, p_hf);
    Ptr4 b12; b12.p[0] = W1; b12.p[1] = W2; b12.p[2] = W1; b12.p[3] = W1;
    sgemm_nt4<<<dim3(2*DFF/64, NTOK/64), 256>>>(p_hf, b12, p_t12, 2*DFF, DMOD, DFF);
    silumul_kernel<<<(NTOK * DFF) / 256, 256>>>();
    // out_h = h2 + t1 @ W3^T (split-K=4)
    sgemm_nt_splitk<<<dim3(DMOD/64, NTOK/64, 4), 256>>>(p_t1, W3, p_part, DMOD, DFF, DFF/4);
    reduce_add<<<(NTOK*DMOD)/256, 256>>>(p_h2, p_part, 4, out, NTOK*DMOD);

    // lu / lv outputs
    copy_uv_kernel<<<(NH * NTOK + 1023) / 1024, 1024>>>(p_lu, p_lv, out + OUT_LU, out + OUT_LV);
}

// round 3
// speedup vs baseline: 1.4485x; 1.1283x over previous
#include <cuda_runtime.h>
#include <cuda_fp16.h>
#include <math.h>

#define NTOK 1280
#define DMOD 512
#define NH   16
#define DH   32
#define DFF  2048
#define NITER 20

// ---------------- scratch ----------------
__device__ __half g_logKh [NH*NTOK*NTOK];   // (h, n, m) fp16
__device__ __half g_logKTh[NH*NTOK*NTOK];   // (h, m, n) fp16
__device__ float g_hn  [NTOK*DMOD];
__device__ float g_qkvg[NTOK*4*DMOD];       // [q | k | v | gate]
__device__ float g_lu [NH*NTOK];
__device__ float g_lv [NH*NTOK];
__device__ float g_xc [NH*NTOK*3];
__device__ float g_rows[NH*NTOK];
__device__ float g_o  [NTOK*DMOD];
__device__ float g_h2 [NTOK*DMOD];
__device__ float g_hf [NTOK*DMOD];
__device__ float g_t12[NTOK*2*DFF];         // [t1 | t2]
__device__ float g_t1 [NTOK*DFF];
__device__ float g_part[4*NTOK*DMOD];       // split-K partials

__constant__ float c_eps[NH] = {0.5f,0.5f,0.5f,0.5f, 1.f,1.f,1.f,1.f,
                                2.f,2.f,2.f,2.f, 4.f,4.f,4.f,4.f};

struct Ptr4 { const float* p[4]; };

// ---------------- utility kernels ----------------
__global__ void zero_kernel(float* p, int n) {
    int i = blockIdx.x * blockDim.x + threadIdx.x;
    if (i < n) p[i] = 0.f;
}

__global__ void copy_uv_kernel(const float* __restrict__ lu, const float* __restrict__ lv,
                               float* __restrict__ o1, float* __restrict__ o2) {
    int i = blockIdx.x * blockDim.x + threadIdx.x;
    if (i < NH*NTOK) { o1[i] = lu[i]; o2[i] = lv[i]; }
}

__global__ void ln_kernel(const float* __restrict__ in, const float* __restrict__ g,
                          const float* __restrict__ b, float* __restrict__ out) {
    int row = blockIdx.x;
    int t = threadIdx.x;
    const float* x = in + (size_t)row * DMOD;
    float v0 = x[t], v1 = x[t + 256];
    __shared__ float red[256];
    red[t] = v0 + v1;
    __syncthreads();
    for (int o = 128; o > 0; o >>= 1) { if (t < o) red[t] += red[t + o]; __syncthreads(); }
    float mean = red[0] * (1.f / DMOD);
    __syncthreads();
    float d0 = v0 - mean, d1 = v1 - mean;
    red[t] = d0 * d0 + d1 * d1;
    __syncthreads();
    for (int o = 128; o > 0; o >>= 1) { if (t < o) red[t] += red[t + o]; __syncthreads(); }
    float r = rsqrtf(red[0] * (1.f / DMOD) + 1e-5f);
    out[(size_t)row * DMOD + t]       = d0 * r * g[t]       + b[t];
    out[(size_t)row * DMOD + t + 256] = d1 * r * g[t + 256] + b[t + 256];
}

// per-head QK layernorm; blockIdx.y selects Q (0) or K (1) section; row stride 4*DMOD
__global__ void qkln_kernel(float* __restrict__ base) {
    int gidx = blockIdx.x * 8 + (threadIdx.x >> 5);
    int lane = threadIdx.x & 31;
    if (gidx >= NTOK * NH) return;
    int n = gidx / NH, h = gidx % NH;
    float* p = base + (size_t)n * (4*DMOD) + blockIdx.y * DMOD + h * DH;
    float v = p[lane];
    float s = v;
    for (int o = 16; o; o >>= 1) s += __shfl_xor_sync(0xffffffffu, s, o);
    float mean = s * (1.f / 32.f);
    float d = v - mean;
    float s2 = d * d;
    for (int o = 16; o; o >>= 1) s2 += __shfl_xor_sync(0xffffffffu, s2, o);
    p[lane] = d * rsqrtf(s2 * (1.f / 32.f) + 1e-5f);
}

// ---------------- TF32 tensor-core GEMM ----------------
__device__ __forceinline__ unsigned f2tf32(float f) {
    unsigned u;
    asm("cvt.rna.tf32.f32 %0, %1;" : "=r"(u) : "f"(f));
    return u;
}

__device__ __forceinline__ void mma_tf32(float c[4], const unsigned a[4], const unsigned b[2]) {
    asm volatile("mma.sync.aligned.m16n8k8.row.col.f32.tf32.tf32.f32 "
        "{%0,%1,%2,%3}, {%4,%5,%6,%7}, {%8,%9}, {%0,%1,%2,%3};"
        : "+f"(c[0]), "+f"(c[1]), "+f"(c[2]), "+f"(c[3])
        : "r"(a[0]), "r"(a[1]), "r"(a[2]), "r"(a[3]), "r"(b[0]), "r"(b[1]));
}

// C[M=1280, Nn] = A[1280,K] @ Bsel[Nn,K]^T, output to C + blockIdx.z*1280*Nn.
// K-chunk [z*KC, (z+1)*KC). BM=128, BN=64, BK=32, 256 threads.
__global__ void tc_gemm(const float* __restrict__ A, Ptr4 B4, float* __restrict__ C,
                        int Nn, int K, int colsPer, int KC) {
    __shared__ float As[32][136];
    __shared__ float Bs[32][72];
    int tid = threadIdx.x;
    int m0 = blockIdx.y * 128, n0 = blockIdx.x * 64;
    const float* B = B4.p[n0 / colsPer] + (size_t)(n0 % colsPer) * K;
    int kbeg = blockIdx.z * KC, kend = kbeg + KC;

    // global-load indexing
    int arow = tid >> 1, akseg = (tid & 1) << 4;           // A: 128 rows x 2 threads (16 k each)
    int brow = tid & 63, bkseg = (tid >> 6) << 3;          // B: 64 rows x 4 threads (8 k each)
    const float* Ap = A + (size_t)(m0 + arow) * K + akseg;
    const float* Bp = B + (size_t)brow * K + bkseg;

    // warp/frag indexing
    int lane = tid & 31, g = lane >> 2, t = lane & 3;
    int wm = tid >> 6;            // 0..3
    int wn = (tid >> 5) & 1;      // 0..1
    int mBase = wm * 32, nBase = wn * 32;

    float c[2][4][4];
#pragma unroll
    for (int mi = 0; mi < 2; mi++)
#pragma unroll
        for (int ni = 0; ni < 4; ni++)
#pragma unroll
            for (int r = 0; r < 4; r++) c[mi][ni][r] = 0.f;

    for (int k0 = kbeg; k0 < kend; k0 += 32) {
        __syncthreads();
        // A tile -> As[k][m] (tf32 bits)
#pragma unroll
        for (int i = 0; i < 4; i++) {
            float4 a4 = *(const float4*)(Ap + k0 + 4 * i);
            As[akseg + 4*i + 0][arow] = __uint_as_float(f2tf32(a4.x));
            As[akseg + 4*i + 1][arow] = __uint_as_float(f2tf32(a4.y));
            As[akseg + 4*i + 2][arow] = __uint_as_float(f2tf32(a4.z));
            As[akseg + 4*i + 3][arow] = __uint_as_float(f2tf32(a4.w));
        }
        // B tile -> Bs[k][n]
#pragma unroll
        for (int i = 0; i < 2; i++) {
            float4 b4 = *(const float4*)(Bp + k0 + 4 * i);
            Bs[bkseg + 4*i + 0][brow] = __uint_as_float(f2tf32(b4.x));
            Bs[bkseg + 4*i + 1][brow] = __uint_as_float(f2tf32(b4.y));
            Bs[bkseg + 4*i + 2][brow] = __uint_as_float(f2tf32(b4.z));
            Bs[bkseg + 4*i + 3][brow] = __uint_as_float(f2tf32(b4.w));
        }
        __syncthreads();
#pragma unroll
        for (int ks = 0; ks < 32; ks += 8) {
            unsigned a[2][4], b[4][2];
#pragma unroll
            for (int mi = 0; mi < 2; mi++) {
                int mo = mBase + mi * 16 + g;
                a[mi][0] = __float_as_uint(As[ks + t][mo]);
                a[mi][1] = __float_as_uint(As[ks + t][mo + 8]);
                a[mi][2] = __float_as_uint(As[ks + t + 4][mo]);
                a[mi][3] = __float_as_uint(As[ks + t + 4][mo + 8]);
            }
#pragma unroll
            for (int ni = 0; ni < 4; ni++) {
                int no = nBase + ni * 8 + g;
                b[ni][0] = __float_as_uint(Bs[ks + t][no]);
                b[ni][1] = __float_as_uint(Bs[ks + t + 4][no]);
            }
#pragma unroll
            for (int mi = 0; mi < 2; mi++)
#pragma unroll
                for (int ni = 0; ni < 4; ni++)
                    mma_tf32(c[mi][ni], a[mi], b[ni]);
        }
    }

    float* Co = C + (size_t)blockIdx.z * NTOK * Nn;
#pragma unroll
    for (int mi = 0; mi < 2; mi++) {
        int r0 = m0 + mBase + mi * 16 + g;
#pragma unroll
        for (int ni = 0; ni < 4; ni++) {
            int col = n0 + nBase + ni * 8 + 2 * t;
            *(float2*)(Co + (size_t)r0 * Nn + col)       = make_float2(c[mi][ni][0], c[mi][ni][1]);
            *(float2*)(Co + (size_t)(r0 + 8) * Nn + col) = make_float2(c[mi][ni][2], c[mi][ni][3]);
        }
    }
}

// out[i] = R[i] + sum_z part[z*n + i]
__global__ void reduce_add(const float* __restrict__ R, const float* __restrict__ part,
                           int Z, float* __restrict__ out, int n) {
    int i = blockIdx.x * 256 + threadIdx.x;
    if (i >= n) return;
    float a = R[i];
    for (int z = 0; z < Z; z++) a += part[(size_t)z * n + i];
    out[i] = a;
}

// ---------------- logK build ----------------
__global__ void build_logk(const float* __restrict__ wrel, const float* __restrict__ xres,
                           const float* __restrict__ wdist) {
    int h = blockIdx.z;
    int n0 = blockIdx.y * 32, m0 = blockIdx.x * 32;
    __shared__ float Qs[32][33], Ks[32][33], S[32][33];
    __shared__ float xa[32][3], xb[32][3];
    int t = threadIdx.x;
    for (int i = t; i < 1024; i += 256) {
        int r = i >> 5, d = i & 31;
        Qs[r][d] = g_qkvg[(size_t)(n0 + r) * (4*DMOD) + h * DH + d];
        Ks[r][d] = g_qkvg[(size_t)(m0 + r) * (4*DMOD) + DMOD + h * DH + d];
    }
    if (t < 96)  { int r = t / 3, c = t % 3; xa[r][c] = xres[(n0 + r) * 3 + c]; }
    if (t >= 96 && t < 192) { int u = t - 96; int r = u / 3, c = u % 3; xb[r][c] = xres[(m0 + r) * 3 + c]; }
    __syncthreads();
    float inve = 1.f / c_eps[h];
    float wd = wdist[h] * 0.01f;
    const float scale = 0.17677669529663687f;
    int tm = t & 31, tn = t >> 5;
#pragma unroll
    for (int rr = 0; rr < 4; rr++) {
        int nl = tn + rr * 8;
        float acc = 0.f;
#pragma unroll
        for (int d = 0; d < 32; d++) acc += Qs[nl][d] * Ks[tm][d];
        float dx = xa[nl][0] - xb[tm][0];
        float dy = xa[nl][1] - xb[tm][1];
        float dz = xa[nl][2] - xb[tm][2];
        float d2 = dx * dx + dy * dy + dz * dz;
        size_t idx = ((size_t)h * NTOK + n0 + nl) * NTOK + m0 + tm;
        float val = (acc * scale + wrel[idx] - wd * d2) * inve;
        g_logKh[idx] = __float2half(val);
        S[nl][tm] = val;
    }
    __syncthreads();
#pragma unroll
    for (int rr = 0; rr < 4; rr++) {
        int ml = tn + rr * 8;
        g_logKTh[((size_t)h * NTOK + m0 + ml) * NTOK + n0 + tm] = __float2half(S[tm][ml]);
    }
}

// ---------------- Sinkhorn ----------------
__device__ __forceinline__ void lse_merge(float& m, float& s, float mo, float so) {
    float d = m - mo;
    float e = __expf(-fabsf(d));
    s = (d >= 0.f) ? (s + so * e) : (so + s * e);
    m = fmaxf(m, mo);
}

__global__ void sinkhorn_pass(const __half* __restrict__ mat, const float* __restrict__ bias,
                              const float* __restrict__ marg, float* __restrict__ out) {
    int h = blockIdx.y;
    __shared__ float bs[NTOK];
    for (int i = threadIdx.x; i < NTOK; i += 256) bs[i] = bias[h * NTOK + i];
    __syncthreads();
    int warp = threadIdx.x >> 5, lane = threadIdx.x & 31;
    int row = blockIdx.x * 8 + warp;
    const uint4* pv = (const uint4*)(mat + ((size_t)h * NTOK + row) * NTOK);
    float m = -1e30f, s = 0.f;
#pragma unroll
    for (int c = 0; c < 5; c++) {
        uint4 u = pv[c * 32 + lane];
        int jb = (c * 32 + lane) * 8;
        const __half2* hh = (const __half2*)&u;
        float2 f0 = __half22float2(hh[0]);
        float2 f1 = __half22float2(hh[1]);
        float2 f2 = __half22float2(hh[2]);
        float2 f3 = __half22float2(hh[3]);
        float x0 = f0.x + bs[jb + 0], x1 = f0.y + bs[jb + 1];
        float x2 = f1.x + bs[jb + 2], x3 = f1.y + bs[jb + 3];
        float x4 = f2.x + bs[jb + 4], x5 = f2.y + bs[jb + 5];
        float x6 = f3.x + bs[jb + 6], x7 = f3.y + bs[jb + 7];
        float ma = fmaxf(x0, x1), sa = 1.f + __expf(-fabsf(x0 - x1));
        float mb = fmaxf(x2, x3), sb = 1.f + __expf(-fabsf(x2 - x3));
        float mc = fmaxf(x4, x5), sc = 1.f + __expf(-fabsf(x4 - x5));
        float md = fmaxf(x6, x7), sd = 1.f + __expf(-fabsf(x6 - x7));
        lse_merge(ma, sa, mb, sb);
        lse_merge(mc, sc, md, sd);
        lse_merge(ma, sa, mc, sc);
        lse_merge(m, s, ma, sa);
    }
    for (int o = 16; o; o >>= 1) {
        float mo = __shfl_xor_sync(0xffffffffu, m, o);
        float so = __shfl_xor_sync(0xffffffffu, s, o);
        lse_merge(m, s, mo, so);
    }
    if (lane == 0) {
        float fi = 1.f / (1.f + c_eps[h]);
        out[h * NTOK + row] = fi * (logf(fmaxf(marg[h * NTOK + row], 1e-8f)) - (m + logf(s)));
    }
}

// ---------------- P application ----------------
__global__ void papply_kernel(const float* __restrict__ xres) {
    int h = blockIdx.y;
    int warp = threadIdx.x >> 5, lane = threadIdx.x & 31;
    int row = blockIdx.x * 8 + warp;
    __shared__ float lvs[NTOK];
    __shared__ float xs[3 * NTOK];
    __shared__ float vs[128 * 32];
    for (int i = threadIdx.x; i < NTOK; i += 256) lvs[i] = g_lv[h * NTOK + i];
    for (int i = threadIdx.x; i < 3 * NTOK; i += 256) xs[i] = xres[i];
    float lu_r = g_lu[h * NTOK + row];
    float acc = 0.f, ax = 0.f, psum = 0.f;
    for (int mc = 0; mc < NTOK; mc += 128) {
        __syncthreads();
        for (int i = threadIdx.x; i < 128 * 32; i += 256) {
            int r = i >> 5, d = i & 31;
            vs[i] = g_qkvg[(size_t)(mc + r) * (4*DMOD) + 2*DMOD + h * DH + d];
        }
        __syncthreads();
        const __half* lk = g_logKh + ((size_t)h * NTOK + row) * NTOK + mc;
#pragma unroll
        for (int mj = 0; mj < 128; mj += 32) {
            float pl = __expf(__half2float(lk[mj + lane]) + lvs[mc + mj + lane] + lu_r);
            psum += pl;
#pragma unroll
            for (int j = 0; j < 32; j++) {
                float p = __shfl_sync(0xffffffffu, pl, j);
                acc += p * vs[(mj + j) * 32 + lane];
                if (lane < 3) ax += p * xs[(mc + mj + j) * 3 + lane];
            }
        }
    }
    float ps = psum;
    for (int o = 16; o; o >>= 1) ps += __shfl_xor_sync(0xffffffffu, ps, o);
    float gt = g_qkvg[(size_t)row * (4*DMOD) + 3*DMOD + h * DH + lane];
    g_o[(size_t)row * DMOD + h * DH + lane] = acc / (1.f + __expf(-gt));
    if (lane < 3) g_xc[((size_t)h * NTOK + row) * 3 + lane] = ax;
    if (lane == 0) g_rows[h * NTOK + row] = ps;
}

__global__ void xout_kernel(const float* __restrict__ xres, const float* __restrict__ gamma,
                            float* __restrict__ out) {
    int n = blockIdx.x * 256 + threadIdx.x;
    if (n >= NTOK) return;
    float x0 = xres[n * 3 + 0], x1 = xres[n * 3 + 1], x2 = xres[n * 3 + 2];
    float a0 = 0.f, a1 = 0.f, a2 = 0.f;
    for (int h = 0; h < NH; h++) {
        float r = 1.f / (g_rows[h * NTOK + n] + 1e-8f);
        float gm = gamma[h];
        a0 += gm * (x0 - g_xc[((size_t)h * NTOK + n) * 3 + 0] * r);
        a1 += gm * (x1 - g_xc[((size_t)h * NTOK + n) * 3 + 1] * r);
        a2 += gm * (x2 - g_xc[((size_t)h * NTOK + n) * 3 + 2] * r);
    }
    out[n * 3 + 0] = x0 + a0;
    out[n * 3 + 1] = x1 + a1;
    out[n * 3 + 2] = x2 + a2;
}

__global__ void silumul_kernel() {
    int i = blockIdx.x * 256 + threadIdx.x;
    if (i < NTOK * DFF) {
        int n = i >> 11, j = i & (DFF - 1);
        float a = g_t12[(size_t)n * (2*DFF) + j];
        float b = g_t12[(size_t)n * (2*DFF) + DFF + j];
        g_t1[i] = a / (1.f + __expf(-a)) * b;
    }
}

// ---------------- launch ----------------
extern "C" void kernel_launch(void* const* d_in, const int* in_sizes, int n_in,
                              void* d_out, int out_size) {
    const float* h_in  = (const float*)d_in[0];
    const float* x_res = (const float*)d_in[1];
    const float* mu    = (const float*)d_in[2];
    const float* nu    = (const float*)d_in[3];
    const float* wrel  = (const float*)d_in[4];
    const float* wdist = (const float*)d_in[5];
    const float* ln_ag = (const float*)d_in[7];
    const float* ln_ab = (const float*)d_in[8];
    const float* Wq    = (const float*)d_in[9];
    const float* Wk    = (const float*)d_in[10];
    const float* Wv    = (const float*)d_in[11];
    const float* Wg    = (const float*)d_in[12];
    const float* Wo    = (const float*)d_in[13];
    const float* gamma = (const float*)d_in[14];
    const float* ln_fg = (const float*)d_in[15];
    const float* ln_fb = (const float*)d_in[16];
    const float* W1    = (const float*)d_in[17];
    const float* W2    = (const float*)d_in[18];
    const float* W3    = (const float*)d_in[19];
    float* out = (float*)d_out;

    __half *p_logKh, *p_logKTh;
    float *p_hn, *p_qkvg, *p_lu, *p_lv, *p_o, *p_h2, *p_hf, *p_t1, *p_part, *p_t12;
    cudaGetSymbolAddress((void**)&p_logKh,  g_logKh);
    cudaGetSymbolAddress((void**)&p_logKTh, g_logKTh);
    cudaGetSymbolAddress((void**)&p_hn,     g_hn);
    cudaGetSymbolAddress((void**)&p_qkvg,   g_qkvg);
    cudaGetSymbolAddress((void**)&p_lu,     g_lu);
    cudaGetSymbolAddress((void**)&p_lv,     g_lv);
    cudaGetSymbolAddress((void**)&p_o,      g_o);
    cudaGetSymbolAddress((void**)&p_h2,     g_h2);
    cudaGetSymbolAddress((void**)&p_hf,     g_hf);
    cudaGetSymbolAddress((void**)&p_t1,     g_t1);
    cudaGetSymbolAddress((void**)&p_part,   g_part);
    cudaGetSymbolAddress((void**)&p_t12,    g_t12);

    const int OUT_X  = NTOK * DMOD;
    const int OUT_LU = OUT_X + NTOK * 3;
    const int OUT_LV = OUT_LU + NH * NTOK;

    zero_kernel<<<(NH * NTOK + 1023) / 1024, 1024>>>(p_lv, NH * NTOK);
    ln_kernel<<<NTOK, 256>>>(h_in, ln_ag, ln_ab, p_hn);

    // QKVG projection: [1280, 2048], tensor cores
    Ptr4 bqkvg; bqkvg.p[0] = Wq; bqkvg.p[1] = Wk; bqkvg.p[2] = Wv; bqkvg.p[3] = Wg;
    tc_gemm<<<dim3(4*DMOD/64, NTOK/128, 1), 256>>>(p_hn, bqkvg, p_qkvg, 4*DMOD, DMOD, DMOD, DMOD);

    // QK layernorm (both sections, one launch)
    qkln_kernel<<<dim3((NTOK * NH) / 8, 2), 256>>>(p_qkvg);

    build_logk<<<dim3(NTOK / 32, NTOK / 32, NH), 256>>>(wrel, x_res, wdist);

    dim3 gsink(NTOK / 8, NH);
    for (int it = 0; it < NITER; it++) {
        sinkhorn_pass<<<gsink, 256>>>(p_logKh,  p_lv, mu, p_lu);
        sinkhorn_pass<<<gsink, 256>>>(p_logKTh, p_lu, nu, p_lv);
    }

    papply_kernel<<<gsink, 256>>>(x_res);

    // h2 = h + o @ Wo^T  (TC, split-K=2)
    Ptr4 bWo; bWo.p[0] = Wo; bWo.p[1] = Wo; bWo.p[2] = Wo; bWo.p[3] = Wo;
    tc_gemm<<<dim3(DMOD/64, NTOK/128, 2), 256>>>(p_o, bWo, p_part, DMOD, DMOD, DMOD, DMOD/2);
    reduce_add<<<(NTOK*DMOD)/256, 256>>>(h_in, p_part, 2, p_h2, NTOK*DMOD);

    xout_kernel<<<(NTOK + 255) / 256, 256>>>(x_res, gamma, out + OUT_X);

    ln_kernel<<<NTOK, 256>>>(p_h2, ln_fg, ln_fb, p_hf);
    Ptr4 b12; b12.p[0] = W1; b12.p[1] = W2; b12.p[2] = W1; b12.p[3] = W1;
    tc_gemm<<<dim3(2*DFF/64, NTOK/128, 1), 256>>>(p_hf, b12, p_t12, 2*DFF, DMOD, DFF, DMOD);
    silumul_kernel<<<(NTOK * DFF) / 256, 256>>>();
    Ptr4 bW3; bW3.p[0] = W3; bW3.p[1] = W3; bW3.p[2] = W3; bW3.p[3] = W3;
    tc_gemm<<<dim3(DMOD/64, NTOK/128, 4), 256>>>(p_t1, bW3, p_part, DMOD, DFF, DMOD, DFF/4);
    reduce_add<<<(NTOK*DMOD)/256, 256>>>(p_h2, p_part, 4, out, NTOK*DMOD);

    copy_uv_kernel<<<(NH * NTOK + 1023) / 1024, 1024>>>(p_lu, p_lv, out + OUT_LU, out + OUT_LV);
}